// round 3
// baseline (speedup 1.0000x reference)
#include <cuda_runtime.h>
#include <cuda_bf16.h>

// ALiBi: out[b,h,i,j] = scores[b,h,i,j] + (j - i) * slopes[h]
// Shapes (fixed by the problem setup): B=2, H=16, S=2048.
// Pure HBM-bound elementwise op: 512 MiB in + 512 MiB out.
//
// Layout: one block per (b,h,i) row. 512 threads/block, each handles one
// float4 (4 consecutive j). Fully coalesced 128B transactions.

static constexpr int S = 2048;        // seq_len
static constexpr int H = 16;          // n_heads
static constexpr int THREADS = 512;   // S/4 float4 lanes per row

__global__ void __launch_bounds__(THREADS, 4)
alibi_kernel(const float* __restrict__ scores,
             const float* __restrict__ slopes,
             float* __restrict__ out)
{
    // row = b*H*S + h*S + i
    const unsigned row = blockIdx.x;
    const int i = row & (S - 1);                 // row within (b,h)
    const int h = (row >> 11) & (H - 1);         // S = 2^11
    const float slope = __ldg(&slopes[h]);       // L1-resident after first hit

    const int j0 = threadIdx.x * 4;              // first column this thread owns
    const size_t base = (size_t)row * S + j0;

    float4 v = *reinterpret_cast<const float4*>(scores + base);

    // bias = (j - i) * slope
    const float d0 = (float)(j0 - i);
    v.x = fmaf(d0,        slope, v.x);
    v.y = fmaf(d0 + 1.0f, slope, v.y);
    v.z = fmaf(d0 + 2.0f, slope, v.z);
    v.w = fmaf(d0 + 3.0f, slope, v.w);

    *reinterpret_cast<float4*>(out + base) = v;
}

extern "C" void kernel_launch(void* const* d_in, const int* in_sizes, int n_in,
                              void* d_out, int out_size)
{
    const float* scores = (const float*)d_in[0];
    const float* slopes = (const float*)d_in[1];
    float* out = (float*)d_out;

    // total elements = B*H*S*S; rows = total / S
    const long long total = (long long)out_size;
    const int rows = (int)(total / S);           // 65536 for B=2,H=16,S=2048

    alibi_kernel<<<rows, THREADS>>>(scores, slopes, out);
}

// round 4
// speedup vs baseline: 1.0498x; 1.0498x over previous
#include <cuda_runtime.h>
#include <cuda_bf16.h>

// ALiBi: out[b,h,i,j] = scores[b,h,i,j] + (j - i) * slopes[h]
// B=2, H=16, S=2048. Pure HBM streaming: 512 MiB in + 512 MiB out.
//
// R3: 4 rows per block, 4 float4 per thread (front-batched -> MLP_p1=4),
// streaming cache hints (no reuse), amortized slope/index math.

static constexpr int S = 2048;
static constexpr int H = 16;
static constexpr int THREADS = 512;
static constexpr int ROWS_PER_BLOCK = 4;      // 512 threads / 128 lanes-per-row
static constexpr int LANES_PER_ROW = 128;     // threads covering one row
static constexpr int UNROLL = 4;              // float4s per thread (one row = 128*4 float4)

__global__ void __launch_bounds__(THREADS, 4)
alibi_kernel(const float* __restrict__ scores,
             const float* __restrict__ slopes,
             float* __restrict__ out)
{
    const int tid  = threadIdx.x;
    const int lane = tid & (LANES_PER_ROW - 1);       // 0..127
    const int rib  = tid >> 7;                        // row within block, 0..3

    const unsigned row = blockIdx.x * ROWS_PER_BLOCK + rib;
    const int i = row & (S - 1);
    const int h = (row >> 11) & (H - 1);
    const float slope = __ldg(&slopes[h]);

    // This thread's 4 float4s: columns j0 + k*512 (k=0..3), all in the same row.
    const int j0 = lane * 4;
    const size_t base = (size_t)row * S + j0;

    const float4* __restrict__ src = reinterpret_cast<const float4*>(scores + base);
    float4*       __restrict__ dst = reinterpret_cast<float4*>(out + base);

    // Front-batch all loads (independent -> 4 outstanding DRAM requests)
    float4 v[UNROLL];
#pragma unroll
    for (int k = 0; k < UNROLL; k++)
        v[k] = __ldcs(src + k * LANES_PER_ROW);       // +k*512 floats = +k*128 float4

    // bias = (j - i) * slope
#pragma unroll
    for (int k = 0; k < UNROLL; k++) {
        const float d0 = (float)(j0 + k * (LANES_PER_ROW * 4) - i);
        v[k].x = fmaf(d0,        slope, v[k].x);
        v[k].y = fmaf(d0 + 1.0f, slope, v[k].y);
        v[k].z = fmaf(d0 + 2.0f, slope, v[k].z);
        v[k].w = fmaf(d0 + 3.0f, slope, v[k].w);
    }

#pragma unroll
    for (int k = 0; k < UNROLL; k++)
        __stcs(dst + k * LANES_PER_ROW, v[k]);

}

extern "C" void kernel_launch(void* const* d_in, const int* in_sizes, int n_in,
                              void* d_out, int out_size)
{
    const float* scores = (const float*)d_in[0];
    const float* slopes = (const float*)d_in[1];
    float* out = (float*)d_out;

    const long long total = (long long)out_size;          // B*H*S*S
    const int rows = (int)(total / S);                    // 65536
    const int blocks = rows / ROWS_PER_BLOCK;             // 16384

    alibi_kernel<<<blocks, THREADS>>>(scores, slopes, out);
}